// round 17
// baseline (speedup 1.0000x reference)
#include <cuda_runtime.h>
#include <cuda_pipeline.h>

#define C 32
#define BMAX 16
#define EPS 1e-5f

// cp.async staging: 8 warps x 3 buffers x 16 rows (2KB) = 48KB static smem.
#define BUF_ROWS 16
#define BUF_BYTES (BUF_ROWS * C * 4)   // 2048
#define NBUF 3

// Scratch (device globals: zero-initialized at module load; the LAST
// normalize block resets them, so every graph replay starts clean).
__device__ float g_sum[BMAX * C];
__device__ float g_sq[BMAX * C];
__device__ float g_cnt[BMAX];
__device__ unsigned int g_done;

// ---------------------------------------------------------------------------
__device__ __forceinline__ void acc4(const float4& v, float4& s, float4& q) {
    s.x += v.x; s.y += v.y; s.z += v.z; s.w += v.w;
    q.x = fmaf(v.x, v.x, q.x); q.y = fmaf(v.y, v.y, q.y);
    q.z = fmaf(v.z, v.z, q.z); q.w = fmaf(v.w, v.w, q.w);
}

// Cross-lane combine + atomic flush for segment b.
__device__ __forceinline__ void flush_stats(float4 s, float4 q, float cnt,
                                            int b, int lane) {
    int sub = lane & 7;
    int rg  = lane >> 3;
    #pragma unroll
    for (int off = 16; off >= 8; off >>= 1) {
        s.x += __shfl_xor_sync(0xffffffffu, s.x, off);
        s.y += __shfl_xor_sync(0xffffffffu, s.y, off);
        s.z += __shfl_xor_sync(0xffffffffu, s.z, off);
        s.w += __shfl_xor_sync(0xffffffffu, s.w, off);
        q.x += __shfl_xor_sync(0xffffffffu, q.x, off);
        q.y += __shfl_xor_sync(0xffffffffu, q.y, off);
        q.z += __shfl_xor_sync(0xffffffffu, q.z, off);
        q.w += __shfl_xor_sync(0xffffffffu, q.w, off);
    }
    if (rg == 0) {
        int b4 = b * C + sub * 4;
        atomicAdd(&g_sum[b4 + 0], s.x);
        atomicAdd(&g_sum[b4 + 1], s.y);
        atomicAdd(&g_sum[b4 + 2], s.z);
        atomicAdd(&g_sum[b4 + 3], s.w);
        atomicAdd(&g_sq[b4 + 0], q.x);
        atomicAdd(&g_sq[b4 + 1], q.y);
        atomicAdd(&g_sq[b4 + 2], q.z);
        atomicAdd(&g_sq[b4 + 3], q.w);
    }
    if (lane == 0) atomicAdd(&g_cnt[b], cnt);
}

// Direct-LDG accumulation (R9 shape) — boundary runs and tails only.
__device__ __forceinline__ void accum_direct(const float* __restrict__ data,
                                             int rs, int re, int lane,
                                             float4& s, float4& q) {
    int rows = re - rs;
    if (rows <= 0) return;
    int sub = lane & 7;
    int rg  = lane >> 3;
    const float4* base = reinterpret_cast<const float4*>(
        data + (size_t)rs * C) + (size_t)rg * 8 + sub;

    int nch = rows >> 3;
    int r = nch << 3;
    if (nch > 0) {
        float4 a = base[0];
        float4 c = base[32];
        for (int k = 1; k < nch; ++k) {
            const float4* p = base + (size_t)k * 64;
            float4 a2 = p[0];
            float4 c2 = p[32];
            acc4(a, s, q); acc4(c, s, q);
            a = a2; c = c2;
        }
        acc4(a, s, q); acc4(c, s, q);
    }
    if (r + 4 <= rows) {
        float4 a = base[(size_t)r * 8];
        acc4(a, s, q);
        r += 4;
    }
    if (r < rows && r + rg < rows) {
        float4 a = base[(size_t)r * 8];
        acc4(a, s, q);
    }
}

// ---------------------------------------------------------------------------
// Kernel 1: per-segment sum / sumsq / count.
// Interior (single-segment) warps stream via warp-private cp.async
// (LDGSTS) 3-buffer pipeline: issue never scoreboard-stalls, so ~2 KB/warp
// stays in flight continuously (the LDG paths plateaued at ~5.2 TB/s on
// exactly this stall across R9-R15). Consumption: conflict-free LDS.128.
// Boundary warps (<=15) binary-search runs and use direct LDG.
// ---------------------------------------------------------------------------
__global__ void __launch_bounds__(256)
reduce_kernel(const float* __restrict__ data,
              const int* __restrict__ bid,
              int N, int rows_per_warp) {
    // [warp][buffer][rows*8 float4] : 8 * 3 * 2048 B = 48 KB
    __shared__ __align__(16) float4 st[8][NBUF][BUF_ROWS * 8];

    int tid = threadIdx.x;
    int wid = tid >> 5;
    int lane = tid & 31;
    int warp = (int)((blockIdx.x * blockDim.x + tid) >> 5);

    int r0 = warp * rows_per_warp;
    if (r0 >= N) return;
    int r1 = r0 + rows_per_warp;
    if (r1 > N) r1 = N;

    int b_first = bid[r0];
    int b_last = bid[r1 - 1];

    float4 s = make_float4(0.f, 0.f, 0.f, 0.f);
    float4 q = make_float4(0.f, 0.f, 0.f, 0.f);

    if (b_first == b_last) {
        int rows = r1 - r0;
        int nb = rows / BUF_ROWS;
        const char* gsrc = reinterpret_cast<const char*>(
            data + (size_t)r0 * C);
        int sub = lane & 7;
        int rg  = lane >> 3;
        unsigned int loff = (unsigned int)lane * 16u;

        // Prologue: fill up to 2 buffers.
        int pre = nb < 2 ? nb : 2;
        for (int j = 0; j < pre; ++j) {
            char* d = reinterpret_cast<char*>(&st[wid][j][0]);
            const char* g = gsrc + (size_t)j * BUF_BYTES;
            #pragma unroll
            for (int r = 0; r < 4; ++r)
                __pipeline_memcpy_async(d + loff + r * 512u,
                                        g + loff + r * 512u, 16);
            __pipeline_commit();
        }

        for (int j = 0; j < nb; ++j) {
            if (j + 1 < nb) __pipeline_wait_prior(1);
            else            __pipeline_wait_prior(0);

            const float4* sb = &st[wid][j % NBUF][0];
            #pragma unroll
            for (int g4 = 0; g4 < 4; ++g4) {
                float4 a = sb[(rg + 4 * g4) * 8 + sub];
                acc4(a, s, q);
            }

            int nx = j + 2;
            if (nx < nb) {
                // Slot (nx % NBUF) was consumed at iteration j-1 (NBUF=3):
                // its ACCs already executed, so rewriting here is safe.
                char* d = reinterpret_cast<char*>(&st[wid][nx % NBUF][0]);
                const char* g = gsrc + (size_t)nx * BUF_BYTES;
                #pragma unroll
                for (int r = 0; r < 4; ++r)
                    __pipeline_memcpy_async(d + loff + r * 512u,
                                            g + loff + r * 512u, 16);
                __pipeline_commit();
            }
        }

        // Tail rows (< BUF_ROWS): direct LDG.
        accum_direct(data, r0 + nb * BUF_ROWS, r1, lane, s, q);
        flush_stats(s, q, (float)rows, b_first, lane);
    } else {
        // Boundary chunk: binary-search each run; direct LDG accumulate.
        float cnt = 0.0f;
        int cur_b = b_first;
        int r = r0;
        while (r < r1) {
            int lo = r + 1, hi = r1;
            while (lo < hi) {
                int mid = (lo + hi) >> 1;     // broadcast load
                if (bid[mid] == cur_b) lo = mid + 1;
                else hi = mid;
            }
            accum_direct(data, r, lo, lane, s, q);
            cnt += (float)(lo - r);
            int nxt = (lo < r1) ? bid[lo] : -1;
            flush_stats(s, q, cnt, cur_b, lane);
            s = make_float4(0.f, 0.f, 0.f, 0.f);
            q = make_float4(0.f, 0.f, 0.f, 0.f);
            cnt = 0.0f;
            r = lo;
            cur_b = nxt;
        }
    }
}

// ---------------------------------------------------------------------------
// Normalize one single-segment run: scale/shift in registers, pure
// LDG.128 -> FMA -> STG.128 with one-chunk lookahead. [At LTS ceiling.]
// ---------------------------------------------------------------------------
__device__ __forceinline__ void norm_run(const float* __restrict__ data,
                                         float* __restrict__ out,
                                         const float4* s_scale,
                                         const float4* s_shift,
                                         int rs, int re, int b, int lane) {
    int rows = re - rs;
    if (rows <= 0) return;
    int sub = lane & 7;
    int rg  = lane >> 3;

    float4 sc = s_scale[b * 8 + sub];
    float4 sh = s_shift[b * 8 + sub];

    const float4* pi = reinterpret_cast<const float4*>(
        data + (size_t)rs * C) + (size_t)rg * 8 + sub;
    float4* po = reinterpret_cast<float4*>(
        out + (size_t)rs * C) + (size_t)rg * 8 + sub;

    int nch = rows >> 3;
    int r = nch << 3;
    if (nch > 0) {
        float4 a = __ldcs(pi);
        float4 c = __ldcs(pi + 32);
        for (int k = 1; k < nch; ++k) {
            const float4* p = pi + (size_t)k * 64;
            float4 a2 = __ldcs(p);
            float4 c2 = __ldcs(p + 32);
            float4 o0, o1;
            o0.x = fmaf(a.x, sc.x, sh.x); o0.y = fmaf(a.y, sc.y, sh.y);
            o0.z = fmaf(a.z, sc.z, sh.z); o0.w = fmaf(a.w, sc.w, sh.w);
            o1.x = fmaf(c.x, sc.x, sh.x); o1.y = fmaf(c.y, sc.y, sh.y);
            o1.z = fmaf(c.z, sc.z, sh.z); o1.w = fmaf(c.w, sc.w, sh.w);
            float4* po_k = po + (size_t)(k - 1) * 64;
            __stcs(po_k, o0);
            __stcs(po_k + 32, o1);
            a = a2; c = c2;
        }
        float4 o0, o1;
        o0.x = fmaf(a.x, sc.x, sh.x); o0.y = fmaf(a.y, sc.y, sh.y);
        o0.z = fmaf(a.z, sc.z, sh.z); o0.w = fmaf(a.w, sc.w, sh.w);
        o1.x = fmaf(c.x, sc.x, sh.x); o1.y = fmaf(c.y, sc.y, sh.y);
        o1.z = fmaf(c.z, sc.z, sh.z); o1.w = fmaf(c.w, sc.w, sh.w);
        float4* po_k = po + (size_t)(nch - 1) * 64;
        __stcs(po_k, o0);
        __stcs(po_k + 32, o1);
    }
    if (r + 4 <= rows) {
        float4 a = __ldcs(pi + (size_t)r * 8);
        float4 o;
        o.x = fmaf(a.x, sc.x, sh.x); o.y = fmaf(a.y, sc.y, sh.y);
        o.z = fmaf(a.z, sc.z, sh.z); o.w = fmaf(a.w, sc.w, sh.w);
        __stcs(po + (size_t)r * 8, o);
        r += 4;
    }
    if (r < rows && r + rg < rows) {
        float4 a = __ldcs(pi + (size_t)r * 8);
        float4 o;
        o.x = fmaf(a.x, sc.x, sh.x); o.y = fmaf(a.y, sc.y, sh.y);
        o.z = fmaf(a.z, sc.z, sh.z); o.w = fmaf(a.w, sc.w, sh.w);
        __stcs(po + (size_t)r * 8, o);
    }
}

// ---------------------------------------------------------------------------
// Kernel 2: normalize + folded finalize (R16-validated). Each block derives
// scale/shift from raw stats; the LAST block resets the accumulators.
// ---------------------------------------------------------------------------
__global__ void normalize_kernel(const float* __restrict__ data,
                                 const int* __restrict__ bid,
                                 const float* __restrict__ w,
                                 const float* __restrict__ bias,
                                 float* __restrict__ out,
                                 int N, int rows_per_warp) {
    __shared__ __align__(16) float sm_scale[BMAX * C];
    __shared__ __align__(16) float sm_shift[BMAX * C];
    __shared__ int sm_last;

    for (int i = threadIdx.x; i < BMAX * C; i += blockDim.x) {
        int b = i >> 5, c = i & 31;
        float cnt = g_cnt[b];
        float norm = 1.0f / (cnt + EPS);
        float sum = g_sum[i];
        float mean = sum * norm;
        float var = (g_sq[i] - 2.0f * mean * sum + mean * mean * cnt) * norm;
        float inv_std = rsqrtf(var + EPS);
        float wc = w ? w[c] : 1.0f;
        float bc = bias ? bias[c] : 0.0f;
        float sc = inv_std * wc;
        sm_scale[i] = sc;
        sm_shift[i] = bc - mean * sc;
    }
    __syncthreads();

    const float4* s_scale = reinterpret_cast<const float4*>(sm_scale);
    const float4* s_shift = reinterpret_cast<const float4*>(sm_shift);

    int warp = (int)((blockIdx.x * blockDim.x + threadIdx.x) >> 5);
    int lane = threadIdx.x & 31;

    int r0 = warp * rows_per_warp;
    if (r0 < N) {
        int r1 = r0 + rows_per_warp;
        if (r1 > N) r1 = N;

        int b_first = bid[r0];
        int b_last = bid[r1 - 1];

        if (b_first == b_last) {
            norm_run(data, out, s_scale, s_shift, r0, r1, b_first, lane);
        } else {
            int r = r0;
            int b = b_first;
            while (r < r1) {
                int lo = r + 1, hi = r1;
                while (lo < hi) {
                    int mid = (lo + hi) >> 1;     // broadcast load
                    if (bid[mid] == b) lo = mid + 1;
                    else hi = mid;
                }
                norm_run(data, out, s_scale, s_shift, r, lo, b, lane);
                r = lo;
                if (r < r1) b = bid[r];
            }
        }
    }

    // Consume-and-reset: last finishing block zeroes the accumulators.
    __syncthreads();
    if (threadIdx.x == 0) {
        unsigned int old = atomicAdd(&g_done, 1u);
        sm_last = (old == gridDim.x - 1) ? 1 : 0;
    }
    __syncthreads();
    if (sm_last) {
        for (int i = threadIdx.x; i < BMAX * C; i += blockDim.x) {
            g_sum[i] = 0.0f;
            g_sq[i] = 0.0f;
        }
        if (threadIdx.x < BMAX) g_cnt[threadIdx.x] = 0.0f;
        if (threadIdx.x == 0) g_done = 0u;
    }
}

// ---------------------------------------------------------------------------
extern "C" void kernel_launch(void* const* d_in, const int* in_sizes, int n_in,
                              void* d_out, int out_size) {
    const float* data = (const float*)d_in[0];
    const int* bid = (const int*)d_in[1];
    int N = in_sizes[0] / C;

    const float* w = nullptr;
    const float* bias = nullptr;
    for (int i = 2; i < n_in; ++i) {
        if (in_sizes[i] == C) {
            if (!w) w = (const float*)d_in[i];
            else if (!bias) bias = (const float*)d_in[i];
        }
    }

    const int threads = 256;

    // Reduce: 4 CTAs/SM (48KB static smem each), cp.async pipeline.
    {
        const int blocks = 148 * 4;
        int warps = blocks * (threads / 32);
        int rpw = (N + warps - 1) / warps;
        reduce_kernel<<<blocks, threads>>>(data, bid, N, rpw);
    }

    // Normalize (+ folded finalize): single wave at 8 blocks/SM.
    {
        const int blocks = 148 * 8;
        int warps = blocks * (threads / 32);
        int rpw = (N + warps - 1) / warps;
        normalize_kernel<<<blocks, threads>>>(data, bid, w, bias,
                                              (float*)d_out, N, rpw);
    }
}